// round 10
// baseline (speedup 1.0000x reference)
#include <cuda_runtime.h>
#include <math.h>
#include <stdint.h>

#define Bb 256
#define Nn 1000
#define Dd 512
#define NEGINF (-INFINITY)
#define NORM_MHA 0.125f
#define NORM_PTR 0.04419417382415922f

static __device__ float g_state[Bb * Dd];
static __device__ float g_Qf[Bb * Dd];
static __device__ float g_Qt[Bb * 8 * Dd];
static __device__ float g_ys2[2 * Bb * 8 * Dd];   // per-half partial ysum
static __device__ float g_m2[2 * Bb * 8];
static __device__ float g_l2[2 * Bb * 8];
static __device__ float g_mhaH[Bb * Dd];
static __device__ float g_mo[Bb * Dd];
static __device__ float g_z[Bb * Dd];
static __device__ float g_tv[Bb * Nn];

// ---------- f32x2 helpers ----------
__device__ __forceinline__ unsigned long long pack2(float a, float b) {
    unsigned long long r;
    asm("mov.b64 %0,{%1,%2};" : "=l"(r) : "f"(a), "f"(b));
    return r;
}
__device__ __forceinline__ void unpack2(unsigned long long v, float& a, float& b) {
    asm("mov.b64 {%0,%1},%2;" : "=f"(a), "=f"(b) : "l"(v));
}
__device__ __forceinline__ void ffma2(unsigned long long& d, unsigned long long a, unsigned long long b) {
    asm("fma.rn.f32x2 %0,%1,%2,%0;" : "+l"(d) : "l"(a), "l"(b));
}
__device__ __forceinline__ void fmul2(unsigned long long& d, unsigned long long a) {
    asm("mul.rn.f32x2 %0,%0,%1;" : "+l"(d) : "l"(a));
}

// ---------- mbarrier + bulk-copy helpers ----------
__device__ __forceinline__ uint32_t smem_u32(const void* p) {
    return (uint32_t)__cvta_generic_to_shared(p);
}
__device__ __forceinline__ void mbar_init(uint32_t a, uint32_t c) {
    asm volatile("mbarrier.init.shared.b64 [%0],%1;" ::"r"(a), "r"(c) : "memory");
}
__device__ __forceinline__ void mbar_expect(uint32_t a, uint32_t bytes) {
    asm volatile("mbarrier.arrive.expect_tx.shared.b64 _,[%0],%1;" ::"r"(a), "r"(bytes) : "memory");
}
__device__ __forceinline__ void mbar_wait(uint32_t a, uint32_t phase) {
    asm volatile(
        "{\n\t.reg .pred P;\n\t"
        "WL%=:\n\t"
        "mbarrier.try_wait.parity.acquire.cta.shared::cta.b64 P,[%0],%1,0x989680;\n\t"
        "@P bra WD%=;\n\t"
        "bra WL%=;\n\t"
        "WD%=:\n\t}"
        ::"r"(a), "r"(phase) : "memory");
}
__device__ __forceinline__ void bulkcp(uint32_t dsh, const void* g, uint32_t n, uint32_t mb) {
    asm volatile("cp.async.bulk.shared::cta.global.mbarrier::complete_tx::bytes [%0],[%1],%2,[%3];"
                 ::"r"(dsh), "l"(g), "r"(n), "r"(mb) : "memory");
}

// fill one 8-token tile (half-batch local): one 2KB bulk copy per UNMASKED row
__device__ __forceinline__ void fill8(const float* __restrict__ Xh, const int* __restrict__ smk,
                                      uint32_t dsh, uint32_t mb, int t, int lane) {
    int ntok = (t == 62) ? 4 : 8;
    int tok = t * 8 + lane;
    bool act = (lane < ntok) && (smk[tok] == 0);
    unsigned bal = __ballot_sync(0xffffffffu, act);
    int cnt = __popc(bal);
    if (cnt == 0) {
        if (lane == 0) {
            mbar_expect(mb, 2048);
            bulkcp(dsh, Xh + (size_t)t * 8 * 512, 2048, mb);
        }
    } else {
        if (lane == 0) mbar_expect(mb, (uint32_t)cnt * 2048);
        __syncwarp();
        if (act) bulkcp(dsh + lane * 2048, Xh + (size_t)tok * 512, 2048, mb);
    }
}

// =============== kS: state = [x0,dc]@W_fc + pool@W_fc1 ; grid(4,32) x 128
__global__ void __launch_bounds__(128) kS(const float* __restrict__ X, const float* __restrict__ pool,
                                          const float* __restrict__ dc, const float* __restrict__ Wfc,
                                          const float* __restrict__ Wfc1) {
    __shared__ float sx[512 * 8], sp[512 * 8], sdc[8];
    int j0 = blockIdx.x * 128, b0 = blockIdx.y * 8, tid = threadIdx.x;
    for (int i = tid; i < 4096; i += 128) {
        int bb = i >> 9, e = i & 511;
        sx[e * 8 + bb] = X[(size_t)(b0 + bb) * (Nn * Dd) + e];
        sp[e * 8 + bb] = pool[(b0 + bb) * Dd + e];
    }
    if (tid < 8) sdc[tid] = dc[b0 + tid];
    __syncthreads();
    int j = j0 + tid;
    float acc[8] = {0, 0, 0, 0, 0, 0, 0, 0};
    for (int e = 0; e < 512; e++) {
        float w0 = Wfc[e * Dd + j], w1 = Wfc1[e * Dd + j];
        float4 a0 = *(const float4*)(sx + e * 8), a1 = *(const float4*)(sx + e * 8 + 4);
        float4 c0 = *(const float4*)(sp + e * 8), c1 = *(const float4*)(sp + e * 8 + 4);
        acc[0] += a0.x * w0 + c0.x * w1; acc[1] += a0.y * w0 + c0.y * w1;
        acc[2] += a0.z * w0 + c0.z * w1; acc[3] += a0.w * w0 + c0.w * w1;
        acc[4] += a1.x * w0 + c1.x * w1; acc[5] += a1.y * w0 + c1.y * w1;
        acc[6] += a1.z * w0 + c1.z * w1; acc[7] += a1.w * w0 + c1.w * w1;
    }
    float wl = Wfc[512 * Dd + j];
#pragma unroll
    for (int bb = 0; bb < 8; bb++) g_state[(b0 + bb) * Dd + j] = acc[bb] + sdc[bb] * wl;
}

// =============== kMM: Out = A@W ; 8 batches/CTA ; grid(4,32) x 128
__global__ void __launch_bounds__(128) kMM(const float* __restrict__ W, int mode) {
    __shared__ float sa[512 * 8];
    const float* A = mode ? g_mhaH : g_state;
    float* Out = mode ? g_mo : g_Qf;
    int j0 = blockIdx.x * 128, b0 = blockIdx.y * 8, tid = threadIdx.x;
    for (int i = tid; i < 4096; i += 128) sa[(i & 511) * 8 + (i >> 9)] = A[(b0 + (i >> 9)) * Dd + (i & 511)];
    __syncthreads();
    int j = j0 + tid;
    float acc[8] = {0, 0, 0, 0, 0, 0, 0, 0};
    for (int f = 0; f < 512; f++) {
        float wv = W[f * Dd + j];
        float4 a0 = *(const float4*)(sa + f * 8), a1 = *(const float4*)(sa + f * 8 + 4);
        acc[0] += a0.x * wv; acc[1] += a0.y * wv; acc[2] += a0.z * wv; acc[3] += a0.w * wv;
        acc[4] += a1.x * wv; acc[5] += a1.y * wv; acc[6] += a1.z * wv; acc[7] += a1.w * wv;
    }
#pragma unroll
    for (int bb = 0; bb < 8; bb++) Out[(b0 + bb) * Dd + j] = acc[bb];
}

// =============== kQt: Qt[b][h][e] ; 8 batches/CTA ; grid(4,32) x 128
__global__ void __launch_bounds__(128) kQt(const float* __restrict__ Wk) {
    __shared__ float sq[8 * 512];
    int e0 = blockIdx.x * 128, b0 = blockIdx.y * 8, tid = threadIdx.x;
    for (int i = tid; i < 4096; i += 128) sq[i] = g_Qf[(b0 + (i >> 9)) * Dd + (i & 511)];
    __syncthreads();
    int e = e0 + tid;
    const float* wrow = Wk + (size_t)e * Dd;
    for (int h = 0; h < 8; h++) {
        float acc[8] = {0, 0, 0, 0, 0, 0, 0, 0};
        const float* wr = wrow + h * 64;
#pragma unroll
        for (int d4 = 0; d4 < 16; d4++) {
            float4 wv = *(const float4*)(wr + d4 * 4);
#pragma unroll
            for (int bb = 0; bb < 8; bb++) {
                float4 q = *(const float4*)(sq + bb * 512 + h * 64 + d4 * 4);
                acc[bb] += wv.x * q.x + wv.y * q.y + wv.z * q.z + wv.w * q.w;
            }
        }
#pragma unroll
        for (int bb = 0; bb < 8; bb++) g_Qt[(size_t)(b0 + bb) * 4096 + h * 512 + e] = acc[bb] * NORM_MHA;
    }
}

// =============== kB: pass 1, half-batch CTAs (grid (2,256) x 256) ===============
// floats: xs[3*4096] | cpart[128] | pbuf[128] | s_m[8] s_l[8] s_scale[16] s_any[2] pad2 | smk[500] | mbar[6]
#define KB_SMEM_FLOATS 13086
__global__ void __launch_bounds__(256, 4) kB(const float* __restrict__ X, const int* __restrict__ mask) {
    extern __shared__ float sm[];
    float* xs = sm;
    float* cpart = sm + 12288;
    float* pbuf = sm + 12416;
    float* s_m = sm + 12544;
    float* s_l = sm + 12552;
    float* s_scale = sm + 12560;
    float* s_any = sm + 12576;
    int* smk = (int*)(sm + 12580);
    uint32_t mb0 = smem_u32(sm + 13080);

    int half = blockIdx.x, b = blockIdx.y;
    int tid = threadIdx.x, w = tid >> 5, lane = tid & 31;
    const float* Xh = X + (size_t)b * (Nn * Dd) + (size_t)half * 500 * Dd;
    const int* mbp = mask + b * Nn + half * 500;
    for (int i = tid; i < 500; i += 256) smk[i] = mbp[i];
    if (tid < 8) { s_m[tid] = NEGINF; s_l[tid] = 0.f; }
    if (tid < 3) mbar_init(mb0 + tid * 8, 1);

    int tg = w >> 2, qh = (w >> 1) & 1, eh = w & 1;
    int e_lo = eh * 256 + (lane << 2);
    unsigned long long qt2[2][8];
    {
        const float* Qtb = g_Qt + (size_t)b * 4096;
        float qv[4][8];
#pragma unroll
        for (int hh = 0; hh < 4; hh++) {
            int h = qh * 4 + hh;
            float4 a = *(const float4*)(Qtb + h * 512 + e_lo);
            float4 c = *(const float4*)(Qtb + h * 512 + e_lo + 128);
            qv[hh][0] = a.x; qv[hh][1] = a.y; qv[hh][2] = a.z; qv[hh][3] = a.w;
            qv[hh][4] = c.x; qv[hh][5] = c.y; qv[hh][6] = c.z; qv[hh][7] = c.w;
        }
#pragma unroll
        for (int e = 0; e < 8; e++) {
            qt2[0][e] = pack2(qv[0][e], qv[1][e]);
            qt2[1][e] = pack2(qv[2][e], qv[3][e]);
        }
    }
    unsigned long long ys64[8];
#pragma unroll
    for (int h = 0; h < 8; h++) ys64[h] = 0ULL;

    __syncthreads();
    uint32_t xs_sh = smem_u32(xs);
    if (w == 0) fill8(Xh, smk, xs_sh, mb0, 0, lane);

    for (int t = 0; t < 63; t++) {
        int t0 = t * 8;
        int ntok = (t == 62) ? 4 : 8;
        int s = t % 3, par = t & 1;
        if (w == 0 && t < 62) {
            int ns = (t + 1) % 3;
            fill8(Xh, smk, xs_sh + ns * 16384, mb0 + ns * 8, t + 1, lane);
        }
        mbar_wait(mb0 + s * 8, (t / 3) & 1);
        if (tid == 0) s_any[par] = 0.f;
        const float* xc = xs + s * 4096;
        // ---- phase 2: compat partials (warp: 4 tokens x 4 heads x 256e-half) ----
#pragma unroll
        for (int k = 0; k < 4; k++) {
            int n = tg * 4 + k;
            if (n >= ntok || smk[t0 + n]) continue;
            const float* row = xc + (n << 9);
            float4 xa = *(const float4*)(row + e_lo);
            float4 xb2 = *(const float4*)(row + e_lo + 128);
            unsigned long long av0 = 0, av1 = 0, xx;
            xx = pack2(xa.x, xa.x); ffma2(av0, xx, qt2[0][0]); ffma2(av1, xx, qt2[1][0]);
            xx = pack2(xa.y, xa.y); ffma2(av0, xx, qt2[0][1]); ffma2(av1, xx, qt2[1][1]);
            xx = pack2(xa.z, xa.z); ffma2(av0, xx, qt2[0][2]); ffma2(av1, xx, qt2[1][2]);
            xx = pack2(xa.w, xa.w); ffma2(av0, xx, qt2[0][3]); ffma2(av1, xx, qt2[1][3]);
            xx = pack2(xb2.x, xb2.x); ffma2(av0, xx, qt2[0][4]); ffma2(av1, xx, qt2[1][4]);
            xx = pack2(xb2.y, xb2.y); ffma2(av0, xx, qt2[0][5]); ffma2(av1, xx, qt2[1][5]);
            xx = pack2(xb2.z, xb2.z); ffma2(av0, xx, qt2[0][6]); ffma2(av1, xx, qt2[1][6]);
            xx = pack2(xb2.w, xb2.w); ffma2(av0, xx, qt2[0][7]); ffma2(av1, xx, qt2[1][7]);
            float a0, a1, a2, a3;
            unpack2(av0, a0, a1); unpack2(av1, a2, a3);
#pragma unroll
            for (int off = 16; off > 0; off >>= 1) {
                a0 += __shfl_xor_sync(0xffffffffu, a0, off);
                a1 += __shfl_xor_sync(0xffffffffu, a1, off);
                a2 += __shfl_xor_sync(0xffffffffu, a2, off);
                a3 += __shfl_xor_sync(0xffffffffu, a3, off);
            }
            if (lane == 0)
                *(float4*)(cpart + (eh * 8 + n) * 8 + qh * 4) = make_float4(a0, a1, a2, a3);
        }
        __syncthreads();
        // ---- phase 3: online softmax (warp = head, lanes 0-7 = tokens) ----
        {
            int h = w;
            float u = NEGINF;
            if (lane < ntok && smk[t0 + lane] == 0) u = cpart[lane * 8 + h] + cpart[64 + lane * 8 + h];
            float tmax = u;
#pragma unroll
            for (int off = 16; off > 0; off >>= 1) tmax = fmaxf(tmax, __shfl_xor_sync(0xffffffffu, tmax, off));
            float m_old = s_m[h], m_new = fmaxf(m_old, tmax);
            float p = (u != NEGINF) ? __expf(u - m_new) : 0.f;
            if (lane < 8) pbuf[par * 64 + lane * 8 + h] = p;
            float ps = p;
#pragma unroll
            for (int off = 16; off > 0; off >>= 1) ps += __shfl_xor_sync(0xffffffffu, ps, off);
            if (lane == 0) {
                float sc = 1.f;
                if (m_new > m_old) { sc = (m_old == NEGINF) ? 1.f : __expf(m_old - m_new); s_m[h] = m_new; }
                s_scale[par * 8 + h] = sc;
                s_l[h] = s_l[h] * sc + ps;
                if (sc != 1.f) s_any[par] = 1.f;
            }
        }
        __syncthreads();
        // ---- phase 4: ysum (all 256 threads, e2 = tid owns 2 e's) ----
        if (s_any[par] != 0.f) {
#pragma unroll
            for (int h = 0; h < 8; h++) {
                float s2 = s_scale[par * 8 + h];
                fmul2(ys64[h], pack2(s2, s2));
            }
        }
        const float* pb = pbuf + par * 64;
        for (int k = 0; k < ntok; k++) {
            if (smk[t0 + k]) continue;
            unsigned long long xv = *(const unsigned long long*)(xc + (k << 9) + (tid << 1));
            float4 p0 = *(const float4*)(pb + (k << 3));
            float4 p1 = *(const float4*)(pb + (k << 3) + 4);
            ffma2(ys64[0], xv, pack2(p0.x, p0.x));
            ffma2(ys64[1], xv, pack2(p0.y, p0.y));
            ffma2(ys64[2], xv, pack2(p0.z, p0.z));
            ffma2(ys64[3], xv, pack2(p0.w, p0.w));
            ffma2(ys64[4], xv, pack2(p1.x, p1.x));
            ffma2(ys64[5], xv, pack2(p1.y, p1.y));
            ffma2(ys64[6], xv, pack2(p1.z, p1.z));
            ffma2(ys64[7], xv, pack2(p1.w, p1.w));
        }
    }
    __syncthreads();
    // epilogue: write partial ysum/m/l for this half
    float* yo = g_ys2 + ((size_t)(half * Bb + b)) * 4096;
#pragma unroll
    for (int h = 0; h < 8; h++) {
        float a, bv;
        unpack2(ys64[h], a, bv);
        *(float2*)(yo + h * 512 + (tid << 1)) = make_float2(a, bv);
    }
    if (tid < 8) {
        g_m2[(half * Bb + b) * 8 + tid] = s_m[tid];
        g_l2[(half * Bb + b) * 8 + tid] = s_l[tid];
    }
}

// =============== kV: merge halves + mhaH = (ysum/l)@Wv ; grid(4,32) x 128
__global__ void __launch_bounds__(128) kV(const float* __restrict__ Wv) {
    __shared__ float syc[2 * 4096];
    __shared__ float s0a[16], s1a[16];
    int h0 = blockIdx.x * 2, b0 = blockIdx.y * 8, tid = threadIdx.x;
    if (tid < 16) {
        int bb = tid >> 1, hl = tid & 1;
        int b = b0 + bb, h = h0 + hl;
        float m0 = g_m2[b * 8 + h], m1 = g_m2[(Bb + b) * 8 + h];
        float l0 = g_l2[b * 8 + h], l1 = g_l2[(Bb + b) * 8 + h];
        float M = fmaxf(m0, m1);
        float e0 = __expf(m0 - M), e1 = __expf(m1 - M);
        float L = l0 * e0 + l1 * e1;
        s0a[tid] = e0 / L;
        s1a[tid] = e1 / L;
    }
    __syncthreads();
    for (int i = tid; i < 8192; i += 128) {
        int hl = i >> 12, bb = (i >> 9) & 7, e = i & 511;
        int b = b0 + bb, h = h0 + hl;
        float v = g_ys2[(size_t)b * 4096 + h * 512 + e] * s0a[bb * 2 + hl]
                + g_ys2[(size_t)(Bb + b) * 4096 + h * 512 + e] * s1a[bb * 2 + hl];
        syc[hl * 4096 + e * 8 + bb] = v;
    }
    __syncthreads();
    int j = blockIdx.x * 128 + tid, hl = tid >> 6;
    const float* base = syc + hl * 4096;
    float acc[8] = {0, 0, 0, 0, 0, 0, 0, 0};
    for (int e = 0; e < 512; e++) {
        float wv = Wv[e * Dd + j];
        float4 y0 = *(const float4*)(base + e * 8), y1 = *(const float4*)(base + e * 8 + 4);
        acc[0] += y0.x * wv; acc[1] += y0.y * wv; acc[2] += y0.z * wv; acc[3] += y0.w * wv;
        acc[4] += y1.x * wv; acc[5] += y1.y * wv; acc[6] += y1.z * wv; acc[7] += y1.w * wv;
    }
#pragma unroll
    for (int bb = 0; bb < 8; bb++) g_mhaH[(b0 + bb) * Dd + j] = acc[bb];
}

// =============== kZ: z = norm_ptr * Wkp@mo ; 8 batches/CTA ; grid(4,32) x 128
__global__ void __launch_bounds__(128) kZ(const float* __restrict__ Wkp) {
    __shared__ float smo[512 * 8];
    int e0 = blockIdx.x * 128, b0 = blockIdx.y * 8, tid = threadIdx.x;
    for (int i = tid; i < 4096; i += 128) smo[(i & 511) * 8 + (i >> 9)] = g_mo[(b0 + (i >> 9)) * Dd + (i & 511)];
    __syncthreads();
    int e = e0 + tid;
    const float* wrow = Wkp + (size_t)e * Dd;
    float acc[8] = {0, 0, 0, 0, 0, 0, 0, 0};
    for (int f = 0; f < 512; f++) {
        float wv = wrow[f];
        float4 m0 = *(const float4*)(smo + f * 8), m1 = *(const float4*)(smo + f * 8 + 4);
        acc[0] += m0.x * wv; acc[1] += m0.y * wv; acc[2] += m0.z * wv; acc[3] += m0.w * wv;
        acc[4] += m1.x * wv; acc[5] += m1.y * wv; acc[6] += m1.z * wv; acc[7] += m1.w * wv;
    }
#pragma unroll
    for (int bb = 0; bb < 8; bb++) g_z[(b0 + bb) * Dd + e] = acc[bb] * NORM_PTR;
}

// =============== kD1: tv[b][n] = tanh(norm*x.z)*10 ; grid(4,256) x 256, barrier-free
__global__ void __launch_bounds__(256, 4) kD1(const float* __restrict__ X, const int* __restrict__ mask) {
    __shared__ int smk[250];
    int q = blockIdx.x, b = blockIdx.y;
    int tid = threadIdx.x, w = tid >> 5, lane = tid & 31;
    const int* mbp = mask + b * Nn + q * 250;
    for (int i = tid; i < 250; i += 256) smk[i] = mbp[i];
    const float* zb = g_z + b * Dd;
    float4 z0 = *(const float4*)(zb + lane * 4);
    float4 z1 = *(const float4*)(zb + 128 + lane * 4);
    float4 z2 = *(const float4*)(zb + 256 + lane * 4);
    float4 z3 = *(const float4*)(zb + 384 + lane * 4);
    const float* Xq = X + (size_t)b * (Nn * Dd) + (size_t)q * 250 * Dd;
    float* tvq = g_tv + b * Nn + q * 250;
    __syncthreads();
    for (int n = w; n < 250; n += 8) {
        if (smk[n]) {
            if (lane == 0) tvq[n] = NEGINF;
            continue;
        }
        const float* row = Xq + (size_t)n * Dd;
        float4 x0 = *(const float4*)(row + lane * 4);
        float4 x1 = *(const float4*)(row + 128 + lane * 4);
        float4 x2 = *(const float4*)(row + 256 + lane * 4);
        float4 x3 = *(const float4*)(row + 384 + lane * 4);
        float acc = x0.x * z0.x + x0.y * z0.y + x0.z * z0.z + x0.w * z0.w
                  + x1.x * z1.x + x1.y * z1.y + x1.z * z1.z + x1.w * z1.w
                  + x2.x * z2.x + x2.y * z2.y + x2.z * z2.z + x2.w * z2.w
                  + x3.x * z3.x + x3.y * z3.y + x3.z * z3.z + x3.w * z3.w;
#pragma unroll
        for (int off = 16; off > 0; off >>= 1) acc += __shfl_xor_sync(0xffffffffu, acc, off);
        if (lane == 0) tvq[n] = tanhf(acc) * 10.f;
    }
}

// =============== kD2: masked softmax over tv ; grid 256 x 512
__global__ void __launch_bounds__(512) kD2(float* __restrict__ out) {
    __shared__ float tvals[Nn];
    __shared__ float red[16];
    __shared__ float bcv;
    int b = blockIdx.x, tid = threadIdx.x, w = tid >> 5, lane = tid & 31;
    const float* tvg = g_tv + b * Nn;
    for (int i = tid; i < Nn; i += 512) tvals[i] = tvg[i];
    __syncthreads();
    float t0v = tvals[tid];
    int n1 = tid + 512;
    float t1v = (n1 < Nn) ? tvals[n1] : NEGINF;
    float wmax = fmaxf(t0v, t1v);
#pragma unroll
    for (int off = 16; off > 0; off >>= 1) wmax = fmaxf(wmax, __shfl_xor_sync(0xffffffffu, wmax, off));
    if (lane == 0) red[w] = wmax;
    __syncthreads();
    if (tid == 0) {
        float m = red[0];
#pragma unroll
        for (int i = 1; i < 16; i++) m = fmaxf(m, red[i]);
        bcv = m;
    }
    __syncthreads();
    float gmax = bcv;
    float ev0 = (t0v == NEGINF) ? 0.f : __expf(t0v - gmax);
    float ev1 = (t1v == NEGINF) ? 0.f : __expf(t1v - gmax);
    float ps = ev0 + ev1;
#pragma unroll
    for (int off = 16; off > 0; off >>= 1) ps += __shfl_xor_sync(0xffffffffu, ps, off);
    __syncthreads();
    if (lane == 0) red[w] = ps;
    __syncthreads();
    if (tid == 0) {
        float s = 0.f;
#pragma unroll
        for (int i = 0; i < 16; i++) s += red[i];
        bcv = 1.f / s;
    }
    __syncthreads();
    float inv = bcv;
    out[b * Nn + tid] = ev0 * inv;
    if (n1 < Nn) out[b * Nn + n1] = ev1 * inv;
}

extern "C" void kernel_launch(void* const* d_in, const int* in_sizes, int n_in,
                              void* d_out, int out_size) {
    const float* X    = (const float*)d_in[0];
    const float* pool = (const float*)d_in[1];
    const float* dc   = (const float*)d_in[2];
    const int*   mask = (const int*)d_in[3];
    const float* Wfc  = (const float*)d_in[4];
    const float* Wfc1 = (const float*)d_in[5];
    const float* Wq   = (const float*)d_in[6];
    const float* Wkm  = (const float*)d_in[7];
    const float* Wv   = (const float*)d_in[8];
    const float* Wo   = (const float*)d_in[9];
    const float* Wkp  = (const float*)d_in[10];
    float* out = (float*)d_out;
    const int KB_SMEM = KB_SMEM_FLOATS * 4;
    cudaFuncSetAttribute(kB, cudaFuncAttributeMaxDynamicSharedMemorySize, KB_SMEM);
    kS<<<dim3(4, 32), 128>>>(X, pool, dc, Wfc, Wfc1);
    kMM<<<dim3(4, 32), 128>>>(Wq, 0);
    kQt<<<dim3(4, 32), 128>>>(Wkm);
    kB<<<dim3(2, 256), 256, KB_SMEM>>>(X, mask);
    kV<<<dim3(4, 32), 128>>>(Wv);
    kMM<<<dim3(4, 32), 128>>>(Wo, 1);
    kZ<<<dim3(4, 32), 128>>>(Wkp);
    kD1<<<dim3(4, 256), 256>>>(X, mask);
    kD2<<<256, 512>>>(out);
}

// round 11
// speedup vs baseline: 1.2188x; 1.2188x over previous
#include <cuda_runtime.h>
#include <math.h>
#include <stdint.h>

#define Bb 256
#define Nn 1000
#define Dd 512
#define NEGINF (-INFINITY)
#define NORM_MHA 0.125f
#define NORM_PTR 0.04419417382415922f

static __device__ float g_state[Bb * Dd];
static __device__ float g_Qf[Bb * Dd];
static __device__ float g_Qt[Bb * 8 * Dd];
static __device__ float g_ys2[2 * Bb * 8 * Dd];
static __device__ float g_m2[2 * Bb * 8];
static __device__ float g_l2[2 * Bb * 8];
static __device__ float g_mhaH[Bb * Dd];
static __device__ float g_mo[Bb * Dd];
static __device__ float g_z[Bb * Dd];
static __device__ float g_tv[Bb * Nn];

// ---------- f32x2 helpers ----------
__device__ __forceinline__ unsigned long long pack2(float a, float b) {
    unsigned long long r;
    asm("mov.b64 %0,{%1,%2};" : "=l"(r) : "f"(a), "f"(b));
    return r;
}
__device__ __forceinline__ void unpack2(unsigned long long v, float& a, float& b) {
    asm("mov.b64 {%0,%1},%2;" : "=f"(a), "=f"(b) : "l"(v));
}
__device__ __forceinline__ void ffma2(unsigned long long& d, unsigned long long a, unsigned long long b) {
    asm("fma.rn.f32x2 %0,%1,%2,%0;" : "+l"(d) : "l"(a), "l"(b));
}
__device__ __forceinline__ void fmul2(unsigned long long& d, unsigned long long a) {
    asm("mul.rn.f32x2 %0,%0,%1;" : "+l"(d) : "l"(a));
}

// ---------- mbarrier + bulk-copy helpers ----------
__device__ __forceinline__ uint32_t smem_u32(const void* p) {
    return (uint32_t)__cvta_generic_to_shared(p);
}
__device__ __forceinline__ void mbar_init(uint32_t a, uint32_t c) {
    asm volatile("mbarrier.init.shared.b64 [%0],%1;" ::"r"(a), "r"(c) : "memory");
}
__device__ __forceinline__ void mbar_expect(uint32_t a, uint32_t bytes) {
    asm volatile("mbarrier.arrive.expect_tx.shared.b64 _,[%0],%1;" ::"r"(a), "r"(bytes) : "memory");
}
__device__ __forceinline__ void mbar_wait(uint32_t a, uint32_t phase) {
    asm volatile(
        "{\n\t.reg .pred P;\n\t"
        "WL%=:\n\t"
        "mbarrier.try_wait.parity.acquire.cta.shared::cta.b64 P,[%0],%1,0x989680;\n\t"
        "@P bra WD%=;\n\t"
        "bra WL%=;\n\t"
        "WD%=:\n\t}"
        ::"r"(a), "r"(phase) : "memory");
}
__device__ __forceinline__ void bulkcp(uint32_t dsh, const void* g, uint32_t n, uint32_t mb) {
    asm volatile("cp.async.bulk.shared::cta.global.mbarrier::complete_tx::bytes [%0],[%1],%2,[%3];"
                 ::"r"(dsh), "l"(g), "r"(n), "r"(mb) : "memory");
}

__device__ __forceinline__ void fill8(const float* __restrict__ Xh, const int* __restrict__ smk,
                                      uint32_t dsh, uint32_t mb, int t, int lane) {
    int ntok = (t == 62) ? 4 : 8;
    int tok = t * 8 + lane;
    bool act = (lane < ntok) && (smk[tok] == 0);
    unsigned bal = __ballot_sync(0xffffffffu, act);
    int cnt = __popc(bal);
    if (cnt == 0) {
        if (lane == 0) {
            mbar_expect(mb, 2048);
            bulkcp(dsh, Xh + (size_t)t * 8 * 512, 2048, mb);
        }
    } else {
        if (lane == 0) mbar_expect(mb, (uint32_t)cnt * 2048);
        __syncwarp();
        if (act) bulkcp(dsh + lane * 2048, Xh + (size_t)tok * 512, 2048, mb);
    }
}

// =============== kS: state = [x0,dc]@W_fc + pool@W_fc1 ; grid(4,32) x 128, f32x2
__global__ void __launch_bounds__(128) kS(const float* __restrict__ X, const float* __restrict__ pool,
                                          const float* __restrict__ dc, const float* __restrict__ Wfc,
                                          const float* __restrict__ Wfc1) {
    __shared__ float sx[512 * 8], sp[512 * 8], sdc[8];
    int j0 = blockIdx.x * 128, b0 = blockIdx.y * 8, tid = threadIdx.x;
    for (int i = tid; i < 4096; i += 128) {
        int bb = i >> 9, e = i & 511;
        sx[e * 8 + bb] = X[(size_t)(b0 + bb) * (Nn * Dd) + e];
        sp[e * 8 + bb] = pool[(b0 + bb) * Dd + e];
    }
    if (tid < 8) sdc[tid] = dc[b0 + tid];
    __syncthreads();
    int j = j0 + tid;
    unsigned long long acc[4] = {0ULL, 0ULL, 0ULL, 0ULL};
    for (int e = 0; e < 512; e++) {
        float w0 = Wfc[e * Dd + j], w1 = Wfc1[e * Dd + j];
        unsigned long long w00 = pack2(w0, w0), w11 = pack2(w1, w1);
        ulonglong2 a0 = *(const ulonglong2*)(sx + e * 8);
        ulonglong2 a1 = *(const ulonglong2*)(sx + e * 8 + 4);
        ulonglong2 c0 = *(const ulonglong2*)(sp + e * 8);
        ulonglong2 c1 = *(const ulonglong2*)(sp + e * 8 + 4);
        ffma2(acc[0], a0.x, w00); ffma2(acc[0], c0.x, w11);
        ffma2(acc[1], a0.y, w00); ffma2(acc[1], c0.y, w11);
        ffma2(acc[2], a1.x, w00); ffma2(acc[2], c1.x, w11);
        ffma2(acc[3], a1.y, w00); ffma2(acc[3], c1.y, w11);
    }
    float wl = Wfc[512 * Dd + j];
#pragma unroll
    for (int p = 0; p < 4; p++) {
        float a, b;
        unpack2(acc[p], a, b);
        g_state[(b0 + 2 * p) * Dd + j] = a + sdc[2 * p] * wl;
        g_state[(b0 + 2 * p + 1) * Dd + j] = b + sdc[2 * p + 1] * wl;
    }
}

// =============== kMM: Out = A@W ; 8 batches/CTA ; grid(4,32) x 128, f32x2
__global__ void __launch_bounds__(128) kMM(const float* __restrict__ W, int mode) {
    __shared__ float sa[512 * 8];
    const float* A = mode ? g_mhaH : g_state;
    float* Out = mode ? g_mo : g_Qf;
    int j0 = blockIdx.x * 128, b0 = blockIdx.y * 8, tid = threadIdx.x;
    for (int i = tid; i < 4096; i += 128) sa[(i & 511) * 8 + (i >> 9)] = A[(b0 + (i >> 9)) * Dd + (i & 511)];
    __syncthreads();
    int j = j0 + tid;
    unsigned long long acc[4] = {0ULL, 0ULL, 0ULL, 0ULL};
    for (int f = 0; f < 512; f++) {
        float wv = W[f * Dd + j];
        unsigned long long ww = pack2(wv, wv);
        ulonglong2 a0 = *(const ulonglong2*)(sa + f * 8);
        ulonglong2 a1 = *(const ulonglong2*)(sa + f * 8 + 4);
        ffma2(acc[0], a0.x, ww); ffma2(acc[1], a0.y, ww);
        ffma2(acc[2], a1.x, ww); ffma2(acc[3], a1.y, ww);
    }
#pragma unroll
    for (int p = 0; p < 4; p++) {
        float a, b;
        unpack2(acc[p], a, b);
        Out[(b0 + 2 * p) * Dd + j] = a;
        Out[(b0 + 2 * p + 1) * Dd + j] = b;
    }
}

// =============== kQt: Qt[b][h][e] ; 8 batches/CTA ; grid(4,32) x 128, f32x2 over d
__global__ void __launch_bounds__(128) kQt(const float* __restrict__ Wk) {
    __shared__ float sq[8 * 512];
    int e0 = blockIdx.x * 128, b0 = blockIdx.y * 8, tid = threadIdx.x;
    for (int i = tid; i < 4096; i += 128) sq[i] = g_Qf[(b0 + (i >> 9)) * Dd + (i & 511)];
    __syncthreads();
    int e = e0 + tid;
    const float* wrow = Wk + (size_t)e * Dd;
    for (int h = 0; h < 8; h++) {
        unsigned long long accp[8];
#pragma unroll
        for (int k = 0; k < 8; k++) accp[k] = 0ULL;
        const float* wr = wrow + h * 64;
#pragma unroll
        for (int d4 = 0; d4 < 16; d4++) {
            float4 wv = *(const float4*)(wr + d4 * 4);
            unsigned long long w01 = pack2(wv.x, wv.y), w23 = pack2(wv.z, wv.w);
#pragma unroll
            for (int bb = 0; bb < 8; bb++) {
                ulonglong2 q2 = *(const ulonglong2*)(sq + bb * 512 + h * 64 + d4 * 4);
                ffma2(accp[bb], w01, q2.x);
                ffma2(accp[bb], w23, q2.y);
            }
        }
#pragma unroll
        for (int bb = 0; bb < 8; bb++) {
            float a, b;
            unpack2(accp[bb], a, b);
            g_Qt[(size_t)(b0 + bb) * 4096 + h * 512 + e] = (a + b) * NORM_MHA;
        }
    }
}

// =============== kB: pass 1, half-batch CTAs (grid (2,256) x 256) — unchanged from R10
#define KB_SMEM_FLOATS 13086
__global__ void __launch_bounds__(256, 4) kB(const float* __restrict__ X, const int* __restrict__ mask) {
    extern __shared__ float sm[];
    float* xs = sm;
    float* cpart = sm + 12288;
    float* pbuf = sm + 12416;
    float* s_m = sm + 12544;
    float* s_l = sm + 12552;
    float* s_scale = sm + 12560;
    float* s_any = sm + 12576;
    int* smk = (int*)(sm + 12580);
    uint32_t mb0 = smem_u32(sm + 13080);

    int half = blockIdx.x, b = blockIdx.y;
    int tid = threadIdx.x, w = tid >> 5, lane = tid & 31;
    const float* Xh = X + (size_t)b * (Nn * Dd) + (size_t)half * 500 * Dd;
    const int* mbp = mask + b * Nn + half * 500;
    for (int i = tid; i < 500; i += 256) smk[i] = mbp[i];
    if (tid < 8) { s_m[tid] = NEGINF; s_l[tid] = 0.f; }
    if (tid < 3) mbar_init(mb0 + tid * 8, 1);

    int tg = w >> 2, qh = (w >> 1) & 1, eh = w & 1;
    int e_lo = eh * 256 + (lane << 2);
    unsigned long long qt2[2][8];
    {
        const float* Qtb = g_Qt + (size_t)b * 4096;
        float qv[4][8];
#pragma unroll
        for (int hh = 0; hh < 4; hh++) {
            int h = qh * 4 + hh;
            float4 a = *(const float4*)(Qtb + h * 512 + e_lo);
            float4 c = *(const float4*)(Qtb + h * 512 + e_lo + 128);
            qv[hh][0] = a.x; qv[hh][1] = a.y; qv[hh][2] = a.z; qv[hh][3] = a.w;
            qv[hh][4] = c.x; qv[hh][5] = c.y; qv[hh][6] = c.z; qv[hh][7] = c.w;
        }
#pragma unroll
        for (int e = 0; e < 8; e++) {
            qt2[0][e] = pack2(qv[0][e], qv[1][e]);
            qt2[1][e] = pack2(qv[2][e], qv[3][e]);
        }
    }
    unsigned long long ys64[8];
#pragma unroll
    for (int h = 0; h < 8; h++) ys64[h] = 0ULL;

    __syncthreads();
    uint32_t xs_sh = smem_u32(xs);
    if (w == 0) fill8(Xh, smk, xs_sh, mb0, 0, lane);

    for (int t = 0; t < 63; t++) {
        int t0 = t * 8;
        int ntok = (t == 62) ? 4 : 8;
        int s = t % 3, par = t & 1;
        if (w == 0 && t < 62) {
            int ns = (t + 1) % 3;
            fill8(Xh, smk, xs_sh + ns * 16384, mb0 + ns * 8, t + 1, lane);
        }
        mbar_wait(mb0 + s * 8, (t / 3) & 1);
        if (tid == 0) s_any[par] = 0.f;
        const float* xc = xs + s * 4096;
#pragma unroll
        for (int k = 0; k < 4; k++) {
            int n = tg * 4 + k;
            if (n >= ntok || smk[t0 + n]) continue;
            const float* row = xc + (n << 9);
            float4 xa = *(const float4*)(row + e_lo);
            float4 xb2 = *(const float4*)(row + e_lo + 128);
            unsigned long long av0 = 0, av1 = 0, xx;
            xx = pack2(xa.x, xa.x); ffma2(av0, xx, qt2[0][0]); ffma2(av1, xx, qt2[1][0]);
            xx = pack2(xa.y, xa.y); ffma2(av0, xx, qt2[0][1]); ffma2(av1, xx, qt2[1][1]);
            xx = pack2(xa.z, xa.z); ffma2(av0, xx, qt2[0][2]); ffma2(av1, xx, qt2[1][2]);
            xx = pack2(xa.w, xa.w); ffma2(av0, xx, qt2[0][3]); ffma2(av1, xx, qt2[1][3]);
            xx = pack2(xb2.x, xb2.x); ffma2(av0, xx, qt2[0][4]); ffma2(av1, xx, qt2[1][4]);
            xx = pack2(xb2.y, xb2.y); ffma2(av0, xx, qt2[0][5]); ffma2(av1, xx, qt2[1][5]);
            xx = pack2(xb2.z, xb2.z); ffma2(av0, xx, qt2[0][6]); ffma2(av1, xx, qt2[1][6]);
            xx = pack2(xb2.w, xb2.w); ffma2(av0, xx, qt2[0][7]); ffma2(av1, xx, qt2[1][7]);
            float a0, a1, a2, a3;
            unpack2(av0, a0, a1); unpack2(av1, a2, a3);
#pragma unroll
            for (int off = 16; off > 0; off >>= 1) {
                a0 += __shfl_xor_sync(0xffffffffu, a0, off);
                a1 += __shfl_xor_sync(0xffffffffu, a1, off);
                a2 += __shfl_xor_sync(0xffffffffu, a2, off);
                a3 += __shfl_xor_sync(0xffffffffu, a3, off);
            }
            if (lane == 0)
                *(float4*)(cpart + (eh * 8 + n) * 8 + qh * 4) = make_float4(a0, a1, a2, a3);
        }
        __syncthreads();
        {
            int h = w;
            float u = NEGINF;
            if (lane < ntok && smk[t0 + lane] == 0) u = cpart[lane * 8 + h] + cpart[64 + lane * 8 + h];
            float tmax = u;
#pragma unroll
            for (int off = 16; off > 0; off >>= 1) tmax = fmaxf(tmax, __shfl_xor_sync(0xffffffffu, tmax, off));
            float m_old = s_m[h], m_new = fmaxf(m_old, tmax);
            float p = (u != NEGINF) ? __expf(u - m_new) : 0.f;
            if (lane < 8) pbuf[par * 64 + lane * 8 + h] = p;
            float ps = p;
#pragma unroll
            for (int off = 16; off > 0; off >>= 1) ps += __shfl_xor_sync(0xffffffffu, ps, off);
            if (lane == 0) {
                float sc = 1.f;
                if (m_new > m_old) { sc = (m_old == NEGINF) ? 1.f : __expf(m_old - m_new); s_m[h] = m_new; }
                s_scale[par * 8 + h] = sc;
                s_l[h] = s_l[h] * sc + ps;
                if (sc != 1.f) s_any[par] = 1.f;
            }
        }
        __syncthreads();
        if (s_any[par] != 0.f) {
#pragma unroll
            for (int h = 0; h < 8; h++) {
                float s2 = s_scale[par * 8 + h];
                fmul2(ys64[h], pack2(s2, s2));
            }
        }
        const float* pb = pbuf + par * 64;
        for (int k = 0; k < ntok; k++) {
            if (smk[t0 + k]) continue;
            unsigned long long xv = *(const unsigned long long*)(xc + (k << 9) + (tid << 1));
            float4 p0 = *(const float4*)(pb + (k << 3));
            float4 p1 = *(const float4*)(pb + (k << 3) + 4);
            ffma2(ys64[0], xv, pack2(p0.x, p0.x));
            ffma2(ys64[1], xv, pack2(p0.y, p0.y));
            ffma2(ys64[2], xv, pack2(p0.z, p0.z));
            ffma2(ys64[3], xv, pack2(p0.w, p0.w));
            ffma2(ys64[4], xv, pack2(p1.x, p1.x));
            ffma2(ys64[5], xv, pack2(p1.y, p1.y));
            ffma2(ys64[6], xv, pack2(p1.z, p1.z));
            ffma2(ys64[7], xv, pack2(p1.w, p1.w));
        }
    }
    __syncthreads();
    float* yo = g_ys2 + ((size_t)(half * Bb + b)) * 4096;
#pragma unroll
    for (int h = 0; h < 8; h++) {
        float a, bv;
        unpack2(ys64[h], a, bv);
        *(float2*)(yo + h * 512 + (tid << 1)) = make_float2(a, bv);
    }
    if (tid < 8) {
        g_m2[(half * Bb + b) * 8 + tid] = s_m[tid];
        g_l2[(half * Bb + b) * 8 + tid] = s_l[tid];
    }
}

// =============== kV: merge halves + mhaH = (ysum/l)@Wv ; grid(4,32) x 128, f32x2
__global__ void __launch_bounds__(128) kV(const float* __restrict__ Wv) {
    __shared__ float syc[2 * 4096];
    __shared__ float s0a[16], s1a[16];
    int h0 = blockIdx.x * 2, b0 = blockIdx.y * 8, tid = threadIdx.x;
    if (tid < 16) {
        int bb = tid >> 1, hl = tid & 1;
        int b = b0 + bb, h = h0 + hl;
        float m0 = g_m2[b * 8 + h], m1 = g_m2[(Bb + b) * 8 + h];
        float l0 = g_l2[b * 8 + h], l1 = g_l2[(Bb + b) * 8 + h];
        float M = fmaxf(m0, m1);
        float e0 = __expf(m0 - M), e1 = __expf(m1 - M);
        float L = l0 * e0 + l1 * e1;
        s0a[tid] = e0 / L;
        s1a[tid] = e1 / L;
    }
    __syncthreads();
    for (int i = tid; i < 8192; i += 128) {
        int hl = i >> 12, bb = (i >> 9) & 7, e = i & 511;
        int b = b0 + bb, h = h0 + hl;
        float v = g_ys2[(size_t)b * 4096 + h * 512 + e] * s0a[bb * 2 + hl]
                + g_ys2[(size_t)(Bb + b) * 4096 + h * 512 + e] * s1a[bb * 2 + hl];
        syc[hl * 4096 + e * 8 + bb] = v;
    }
    __syncthreads();
    int j = blockIdx.x * 128 + tid, hl = tid >> 6;
    const float* base = syc + hl * 4096;
    unsigned long long acc[4] = {0ULL, 0ULL, 0ULL, 0ULL};
    for (int e = 0; e < 512; e++) {
        float wv = Wv[e * Dd + j];
        unsigned long long ww = pack2(wv, wv);
        ulonglong2 y0 = *(const ulonglong2*)(base + e * 8);
        ulonglong2 y1 = *(const ulonglong2*)(base + e * 8 + 4);
        ffma2(acc[0], y0.x, ww); ffma2(acc[1], y0.y, ww);
        ffma2(acc[2], y1.x, ww); ffma2(acc[3], y1.y, ww);
    }
#pragma unroll
    for (int p = 0; p < 4; p++) {
        float a, b;
        unpack2(acc[p], a, b);
        g_mhaH[(b0 + 2 * p) * Dd + j] = a;
        g_mhaH[(b0 + 2 * p + 1) * Dd + j] = b;
    }
}

// =============== kZ: z = norm_ptr * Wkp@mo ; grid(4,32) x 128, f32x2
__global__ void __launch_bounds__(128) kZ(const float* __restrict__ Wkp) {
    __shared__ float smo[512 * 8];
    int e0 = blockIdx.x * 128, b0 = blockIdx.y * 8, tid = threadIdx.x;
    for (int i = tid; i < 4096; i += 128) smo[(i & 511) * 8 + (i >> 9)] = g_mo[(b0 + (i >> 9)) * Dd + (i & 511)];
    __syncthreads();
    int e = e0 + tid;
    const float* wrow = Wkp + (size_t)e * Dd;
    unsigned long long acc[4] = {0ULL, 0ULL, 0ULL, 0ULL};
    for (int f = 0; f < 512; f++) {
        float wv = wrow[f];
        unsigned long long ww = pack2(wv, wv);
        ulonglong2 m0 = *(const ulonglong2*)(smo + f * 8);
        ulonglong2 m1 = *(const ulonglong2*)(smo + f * 8 + 4);
        ffma2(acc[0], m0.x, ww); ffma2(acc[1], m0.y, ww);
        ffma2(acc[2], m1.x, ww); ffma2(acc[3], m1.y, ww);
    }
#pragma unroll
    for (int p = 0; p < 4; p++) {
        float a, b;
        unpack2(acc[p], a, b);
        g_z[(b0 + 2 * p) * Dd + e] = a * NORM_PTR;
        g_z[(b0 + 2 * p + 1) * Dd + e] = b * NORM_PTR;
    }
}

// =============== kD1: tv = tanh(x.z)*10 ; grid(4,256) x 256 ; 4 rows/warp-group, batched reduce
__global__ void __launch_bounds__(256) kD1(const float* __restrict__ X, const int* __restrict__ mask) {
    __shared__ int smk[250];
    int q = blockIdx.x, b = blockIdx.y;
    int tid = threadIdx.x, w = tid >> 5, lane = tid & 31;
    const int* mbp = mask + b * Nn + q * 250;
    for (int i = tid; i < 250; i += 256) smk[i] = mbp[i];
    const float* zb = g_z + b * Dd;
    float4 z[4];
#pragma unroll
    for (int c = 0; c < 4; c++) z[c] = *(const float4*)(zb + c * 128 + lane * 4);
    const float* Xq = X + (size_t)b * (Nn * Dd) + (size_t)q * 250 * Dd;
    float* tvq = g_tv + b * Nn + q * 250;
    __syncthreads();
    // groups of 4 rows; 63 groups (last has 2 rows)
    for (int g = w; g < 63; g += 8) {
        int n0 = g * 4;
        int nr = (g == 62) ? 2 : 4;
        int m[4];
        float acc[4] = {0.f, 0.f, 0.f, 0.f};
#pragma unroll
        for (int r = 0; r < 4; r++) m[r] = (r < nr) ? smk[n0 + r] : 1;
#pragma unroll
        for (int c = 0; c < 4; c++) {   // chunk-interleaved: 4 independent loads in flight
            float4 xr[4];
#pragma unroll
            for (int r = 0; r < 4; r++)
                if (!m[r]) xr[r] = *(const float4*)(Xq + (size_t)(n0 + r) * Dd + c * 128 + lane * 4);
#pragma unroll
            for (int r = 0; r < 4; r++)
                if (!m[r])
                    acc[r] += xr[r].x * z[c].x + xr[r].y * z[c].y + xr[r].z * z[c].z + xr[r].w * z[c].w;
        }
#pragma unroll
        for (int off = 16; off > 0; off >>= 1) {
#pragma unroll
            for (int r = 0; r < 4; r++) acc[r] += __shfl_xor_sync(0xffffffffu, acc[r], off);
        }
        if (lane == 0) {
#pragma unroll
            for (int r = 0; r < 4; r++)
                if (r < nr) tvq[n0 + r] = m[r] ? NEGINF : tanhf(acc[r]) * 10.f;
        }
    }
}

// =============== kD2: masked softmax over tv ; grid 256 x 512
__global__ void __launch_bounds__(512) kD2(float* __restrict__ out) {
    __shared__ float tvals[Nn];
    __shared__ float red[16];
    __shared__ float bcv;
    int b = blockIdx.x, tid = threadIdx.x, w = tid >> 5, lane = tid & 31;
    const float* tvg = g_tv + b * Nn;
    for (int i = tid; i < Nn; i += 512) tvals[i] = tvg[i];
    __syncthreads();
    float t0v = tvals[tid];
    int n1 = tid + 512;
    float t1v = (n1 < Nn) ? tvals[n1] : NEGINF;
    float wmax = fmaxf(t0v, t1v);
#pragma unroll
    for (int off = 16; off > 0; off >>= 1) wmax = fmaxf(wmax, __shfl_xor_sync(0xffffffffu, wmax, off));
    if (lane == 0) red[w] = wmax;
    __syncthreads();
    if (tid == 0) {
        float m = red[0];
#pragma unroll
        for (int i = 1; i < 16; i++) m = fmaxf(m, red[i]);
        bcv = m;
    }
    __syncthreads();
    float gmax = bcv;
    float ev0 = (t0v == NEGINF) ? 0.f : __expf(t0v - gmax);
    float ev1 = (t1v == NEGINF) ? 0.f : __expf(t1v - gmax);
    float ps = ev0 + ev1;
#pragma unroll
    for (int off = 16; off > 0; off >>= 1) ps += __shfl_xor_sync(0xffffffffu, ps, off);
    __syncthreads();
    if (lane == 0) red[w] = ps;
    __syncthreads();
    if (tid == 0) {
        float s = 0.f;
#pragma unroll
        for (int i = 0; i < 16; i++) s += red[i];
        bcv = 1.f / s;
    }
    __syncthreads();
    float inv = bcv;
    out[b * Nn + tid] = ev0 * inv;
    if (n1 < Nn) out[b * Nn + n1] = ev1 * inv;
}

extern "C" void kernel_launch(void* const* d_in, const int* in_sizes, int n_in,
                              void* d_out, int out_size) {
    const float* X    = (const float*)d_in[0];
    const float* pool = (const float*)d_in[1];
    const float* dc   = (const float*)d_in[2];
    const int*   mask = (const int*)d_in[3];
    const float* Wfc  = (const float*)d_in[4];
    const float* Wfc1 = (const float*)d_in[5];
    const float* Wq   = (const float*)d_in[6];
    const float* Wkm  = (const float*)d_in[7];
    const float* Wv   = (const float*)d_in[8];
    const float* Wo   = (const float*)d_in[9];
    const float* Wkp  = (const float*)d_in[10];
    float* out = (float*)d_out;
    const int KB_SMEM = KB_SMEM_FLOATS * 4;
    cudaFuncSetAttribute(kB, cudaFuncAttributeMaxDynamicSharedMemorySize, KB_SMEM);
    kS<<<dim3(4, 32), 128>>>(X, pool, dc, Wfc, Wfc1);
    kMM<<<dim3(4, 32), 128>>>(Wq, 0);
    kQt<<<dim3(4, 32), 128>>>(Wkm);
    kB<<<dim3(2, 256), 256, KB_SMEM>>>(X, mask);
    kV<<<dim3(4, 32), 128>>>(Wv);
    kMM<<<dim3(4, 32), 128>>>(Wo, 1);
    kZ<<<dim3(4, 32), 128>>>(Wkp);
    kD1<<<dim3(4, 256), 256>>>(X, mask);
    kD2<<<256, 512>>>(out);
}